// round 7
// baseline (speedup 1.0000x reference)
#include <cuda_runtime.h>
#include <stdint.h>

// SkipGramNS: out[i] = dot(cxt_weight[ctx_idx[i]], tgt_weight[tgt_idx[i]])
// N=1e6, D=128, V=1e5.
//
// R7: persistent warps + 2-deep software pipeline over the proven R3 load
// geometry (8-lane groups x LDG.128 = one full 128B line per row per
// instruction; 4 pairs per warp per iteration). While stage k's loads are in
// flight, stage k+1's loads are issued -> no full-L2-latency bubble per
// batch, no CTA launch/drain gaps.

__device__ __forceinline__ void load_stage(
    const int* __restrict__ ci, const int* __restrict__ ti,
    const float* __restrict__ cw, const float* __restrict__ tw,
    int pair, int j, float4 (&a)[4], float4 (&b)[4])
{
    const long long c = (long long)__ldg(&ci[pair]);
    const long long t = (long long)__ldg(&ti[pair]);
    const float4* __restrict__ cv = reinterpret_cast<const float4*>(cw + c * 128);
    const float4* __restrict__ tv = reinterpret_cast<const float4*>(tw + t * 128);
    #pragma unroll
    for (int k = 0; k < 4; k++) a[k] = __ldg(&cv[j + 8 * k]);
    #pragma unroll
    for (int k = 0; k < 4; k++) b[k] = __ldg(&tv[j + 8 * k]);
}

__device__ __forceinline__ void consume_stage(
    float* __restrict__ out, int pair, int n, int j,
    const float4 (&a)[4], const float4 (&b)[4])
{
    float s0 = 0.f, s1 = 0.f, s2 = 0.f, s3 = 0.f;
    s0 = fmaf(a[0].x, b[0].x, s0); s0 = fmaf(a[0].y, b[0].y, s0);
    s0 = fmaf(a[0].z, b[0].z, s0); s0 = fmaf(a[0].w, b[0].w, s0);
    s1 = fmaf(a[1].x, b[1].x, s1); s1 = fmaf(a[1].y, b[1].y, s1);
    s1 = fmaf(a[1].z, b[1].z, s1); s1 = fmaf(a[1].w, b[1].w, s1);
    s2 = fmaf(a[2].x, b[2].x, s2); s2 = fmaf(a[2].y, b[2].y, s2);
    s2 = fmaf(a[2].z, b[2].z, s2); s2 = fmaf(a[2].w, b[2].w, s2);
    s3 = fmaf(a[3].x, b[3].x, s3); s3 = fmaf(a[3].y, b[3].y, s3);
    s3 = fmaf(a[3].z, b[3].z, s3); s3 = fmaf(a[3].w, b[3].w, s3);
    float s = (s0 + s1) + (s2 + s3);

    // butterfly reduce across the 8-lane group (xor 4,2,1 stays in-group)
    s += __shfl_xor_sync(0xFFFFFFFFu, s, 4);
    s += __shfl_xor_sync(0xFFFFFFFFu, s, 2);
    s += __shfl_xor_sync(0xFFFFFFFFu, s, 1);

    if (j == 0 && pair < n)
        __stcs(&out[pair], s);
}

__global__ void __launch_bounds__(256)
skipgram_dot_kernel(const int* __restrict__ ctx_idx,
                    const int* __restrict__ tgt_idx,
                    const float* __restrict__ cxt_w,
                    const float* __restrict__ tgt_w,
                    float* __restrict__ out,
                    int n, int total_warps)
{
    const int warp_id = (blockIdx.x * blockDim.x + threadIdx.x) >> 5;
    const int lane    = threadIdx.x & 31;
    const int group   = lane >> 3;   // 0..3: pair slot within warp
    const int j       = lane & 7;    // 0..7: lane within group

    const int stride = total_warps * 4;   // pairs consumed per sweep
    int base = warp_id * 4;               // warp-uniform
    if (base >= n) return;                // uniform exit

    float4 A0[4], B0[4], A1[4], B1[4];

    int p0 = base + group;
    load_stage(ctx_idx, tgt_idx, cxt_w, tgt_w, min(p0, n - 1), j, A0, B0);

    for (;;) {
        // stage 1: prefetch next sweep while stage 0 is in flight
        const int b1 = base + stride;            // uniform
        const bool have1 = (b1 < n);
        const int p1 = b1 + group;
        if (have1)
            load_stage(ctx_idx, tgt_idx, cxt_w, tgt_w, min(p1, n - 1), j, A1, B1);

        consume_stage(out, p0, n, j, A0, B0);
        if (!have1) break;

        // stage 0: prefetch the sweep after that
        const int b2 = b1 + stride;               // uniform
        const bool have2 = (b2 < n);
        const int p2 = b2 + group;
        if (have2)
            load_stage(ctx_idx, tgt_idx, cxt_w, tgt_w, min(p2, n - 1), j, A0, B0);

        consume_stage(out, p1, n, j, A1, B1);
        if (!have2) break;

        base = b2;
        p0 = p2;
    }
}

extern "C" void kernel_launch(void* const* d_in, const int* in_sizes, int n_in,
                              void* d_out, int out_size)
{
    const int*   ctx_idx = (const int*)d_in[0];
    const int*   tgt_idx = (const int*)d_in[1];
    const float* cxt_w   = (const float*)d_in[2];
    const float* tgt_w   = (const float*)d_in[3];
    float*       out     = (float*)d_out;

    const int n = in_sizes[0];                  // 1,000,000 pairs
    const int threads = 256;                    // 8 warps/block
    const int blocks  = 148 * 3;                // persistent-ish: 444 CTAs
    const int total_warps = blocks * (threads / 32);

    skipgram_dot_kernel<<<blocks, threads>>>(ctx_idx, tgt_idx, cxt_w, tgt_w,
                                             out, n, total_warps);
}